// round 8
// baseline (speedup 1.0000x reference)
#include <cuda_runtime.h>
#include <math.h>

// ---------------- problem constants ----------------
// B=2, T=2048, C=2048, NH=16, HS=128, NLQ=512, NLKV=512, DHR=64
#define T_LEN 2048
#define BT    4096          // B*T
#define DQK   576           // 512 latent + 64 rope

typedef long long ll;

// ---------------- scratch (device globals; no allocs allowed) ----------------
__device__ float g_cq   [4096 * 512];          // c_q              (B*T, 512)
__device__ float g_ckr  [4096 * 64];           // c_kr             (B*T, 64)
__device__ float g_cqr  [4096 * 1024];         // c_qr             (B*T, 1024)
__device__ float g_Kbig [2 * 2048 * 576];      // [c_kv | rope(kr)] per (b,s)
__device__ float g_Qbig [32 * 2048 * 576];     // per (b,h,t): [scale*qk | scale*rope(qr)]
__device__ float g_keff [16 * 512 * 512];      // k_eff[h,q,k]
__device__ float g_veff [16 * 512 * 128];      // v_eff[h,k,d]
__device__ float g_scores[32 * 2048 * 2048];   // attention probs (512 MB)
__device__ float g_ctx  [32 * 2048 * 512];     // ctx[b,h,t,k]

#define F_CAUSAL 1   // skip tiles strictly above diagonal
#define F_KTRUNC 2   // limit K loop to (bm+1)*tile  (P@V: P zero beyond s=t)
#define F_AK     4   // A: k contiguous (saK==1)   else m contiguous (saM==1)
#define F_BK     8   // B: k contiguous (sbK==1)   else n contiguous (sbN==1)

// =====================================================================
// 128x128x8 double-buffered fp32 GEMM, 256 threads, 8x8 per thread
// (as 2x2 quads of 4x4 for conflict-free LDS.128). Requires:
//   M % 128 == 0, N % 128 == 0, K % 8 == 0
//   float4-alignment of all operand rows (all strides multiples of 4)
// =====================================================================
#define GBM 128
#define GBN 128
#define GBK 8

__global__ void __launch_bounds__(256)
gemm128_k(int M, int N, int K,
          const float* __restrict__ A, int saM, int saK, ll saZ1, ll saZ2,
          const float* __restrict__ B, int sbK, int sbN, ll sbZ1, ll sbZ2,
          float* __restrict__ C, int scM, int scN, ll scZ1, ll scZ2,
          int zdiv, float alpha, int flags)
{
    const int bn = blockIdx.x, bm = blockIdx.y, z = blockIdx.z;
    if ((flags & F_CAUSAL) && bn > bm) return;

    const int z1 = z / zdiv, z2 = z % zdiv;
    A += z1 * saZ1 + z2 * saZ2;
    B += z1 * sbZ1 + z2 * sbZ2;
    C += z1 * scZ1 + z2 * scZ2;

    const int Kuse = (flags & F_KTRUNC) ? min(K, (bm + 1) * GBM) : K;

    __shared__ float As[2][GBK][GBM];
    __shared__ float Bs[2][GBK][GBN];

    const int tid = threadIdx.x;
    const int tx = tid & 15, ty = tid >> 4;
    const int rowA = bm * GBM;
    const int colB = bn * GBN;

    // global-load index precompute
    const int aM  = tid >> 1;            // F_AK path: row
    const int aK4 = (tid & 1) * 4;       // F_AK path: k quad
    const int aM4 = (tid & 31) * 4;      // m-contig path
    const int aKK = tid >> 5;
    const int bN  = tid >> 1;
    const int bK4 = (tid & 1) * 4;
    const int bN4 = (tid & 31) * 4;
    const int bKK = tid >> 5;

    float acc[2][2][4][4] = {};

    float4 pa, pb;
    // prologue load (k0 = 0)
    if (flags & F_AK) pa = *(const float4*)&A[(ll)(rowA + aM) * saM + aK4];
    else              pa = *(const float4*)&A[(ll)aKK * saK + (rowA + aM4)];
    if (flags & F_BK) pb = *(const float4*)&B[(ll)(colB + bN) * sbN + bK4];
    else              pb = *(const float4*)&B[(ll)bKK * sbK + (colB + bN4)];

    if (flags & F_AK) {
        As[0][aK4 + 0][aM] = pa.x; As[0][aK4 + 1][aM] = pa.y;
        As[0][aK4 + 2][aM] = pa.z; As[0][aK4 + 3][aM] = pa.w;
    } else {
        *(float4*)&As[0][aKK][aM4] = pa;
    }
    if (flags & F_BK) {
        Bs[0][bK4 + 0][bN] = pb.x; Bs[0][bK4 + 1][bN] = pb.y;
        Bs[0][bK4 + 2][bN] = pb.z; Bs[0][bK4 + 3][bN] = pb.w;
    } else {
        *(float4*)&Bs[0][bKK][bN4] = pb;
    }
    __syncthreads();

    int buf = 0;
    for (int k0 = 0; k0 < Kuse; k0 += GBK) {
        const bool nxt = (k0 + GBK) < Kuse;
        if (nxt) {
            const int kn = k0 + GBK;
            if (flags & F_AK) pa = *(const float4*)&A[(ll)(rowA + aM) * saM + (kn + aK4)];
            else              pa = *(const float4*)&A[(ll)(kn + aKK) * saK + (rowA + aM4)];
            if (flags & F_BK) pb = *(const float4*)&B[(ll)(colB + bN) * sbN + (kn + bK4)];
            else              pb = *(const float4*)&B[(ll)(kn + bKK) * sbK + (colB + bN4)];
        }

        #pragma unroll
        for (int kk = 0; kk < GBK; kk++) {
            float4 a0 = *(const float4*)&As[buf][kk][ty * 4];
            float4 a1 = *(const float4*)&As[buf][kk][64 + ty * 4];
            float4 b0 = *(const float4*)&Bs[buf][kk][tx * 4];
            float4 b1 = *(const float4*)&Bs[buf][kk][64 + tx * 4];
            float av[2][4] = {{a0.x, a0.y, a0.z, a0.w}, {a1.x, a1.y, a1.z, a1.w}};
            float bv[2][4] = {{b0.x, b0.y, b0.z, b0.w}, {b1.x, b1.y, b1.z, b1.w}};
            #pragma unroll
            for (int ih = 0; ih < 2; ih++)
                #pragma unroll
                for (int i = 0; i < 4; i++)
                    #pragma unroll
                    for (int jh = 0; jh < 2; jh++)
                        #pragma unroll
                        for (int j = 0; j < 4; j++)
                            acc[ih][jh][i][j] += av[ih][i] * bv[jh][j];
        }

        if (nxt) {
            const int nb = buf ^ 1;
            if (flags & F_AK) {
                As[nb][aK4 + 0][aM] = pa.x; As[nb][aK4 + 1][aM] = pa.y;
                As[nb][aK4 + 2][aM] = pa.z; As[nb][aK4 + 3][aM] = pa.w;
            } else {
                *(float4*)&As[nb][aKK][aM4] = pa;
            }
            if (flags & F_BK) {
                Bs[nb][bK4 + 0][bN] = pb.x; Bs[nb][bK4 + 1][bN] = pb.y;
                Bs[nb][bK4 + 2][bN] = pb.z; Bs[nb][bK4 + 3][bN] = pb.w;
            } else {
                *(float4*)&Bs[nb][bKK][bN4] = pb;
            }
        }
        __syncthreads();
        buf ^= 1;
    }

    // ---- epilogue ----
    if (scN == 1) {
        #pragma unroll
        for (int ih = 0; ih < 2; ih++)
            #pragma unroll
            for (int i = 0; i < 4; i++) {
                ll row = rowA + ih * 64 + ty * 4 + i;
                #pragma unroll
                for (int jh = 0; jh < 2; jh++) {
                    ll col = colB + jh * 64 + tx * 4;
                    float4 v = make_float4(alpha * acc[ih][jh][i][0],
                                           alpha * acc[ih][jh][i][1],
                                           alpha * acc[ih][jh][i][2],
                                           alpha * acc[ih][jh][i][3]);
                    *(float4*)&C[row * scM + col] = v;
                }
            }
    } else {
        #pragma unroll
        for (int ih = 0; ih < 2; ih++)
            #pragma unroll
            for (int i = 0; i < 4; i++) {
                ll row = rowA + ih * 64 + ty * 4 + i;
                #pragma unroll
                for (int jh = 0; jh < 2; jh++)
                    #pragma unroll
                    for (int j = 0; j < 4; j++) {
                        ll col = colB + jh * 64 + tx * 4 + j;
                        C[row * scM + col * scN] = alpha * acc[ih][jh][i][j];
                    }
            }
    }
}

// =====================================================================
// legacy 64x64x16 kernel — kept for the one N=64 GEMM (c_kr)
// =====================================================================
#define BM 64
#define BN 64
#define BK 16

__global__ void __launch_bounds__(256)
gemm_k(int M, int N, int K,
       const float* __restrict__ A, int saM, int saK, ll saZ1, ll saZ2,
       const float* __restrict__ B, int sbK, int sbN, ll sbZ1, ll sbZ2,
       float* __restrict__ C, int scM, int scN, ll scZ1, ll scZ2,
       int zdiv, float alpha, int flags)
{
    const int bn = blockIdx.x, bm = blockIdx.y, z = blockIdx.z;
    if ((flags & F_CAUSAL) && bn > bm) return;

    const int z1 = z / zdiv, z2 = z % zdiv;
    A += z1 * saZ1 + z2 * saZ2;
    B += z1 * sbZ1 + z2 * sbZ2;
    C += z1 * scZ1 + z2 * scZ2;

    const int Kuse = (flags & F_KTRUNC) ? min(K, (bm + 1) * BM) : K;

    __shared__ float As[BK][BM + 4];
    __shared__ float Bs[BK][BN + 4];

    const int tid = threadIdx.x;
    const int tx = tid & 15, ty = tid >> 4;
    const int rowA = bm * BM;
    const int colB = bn * BN;

    float acc[4][4] = {};

    for (int k0 = 0; k0 < Kuse; k0 += BK) {
        #pragma unroll
        for (int r = 0; r < 4; r++) {
            int idx = tid + r * 256;
            int m, kk;
            if (flags & F_AK) { kk = idx & 15; m = idx >> 4; }
            else              { m = idx & 63;  kk = idx >> 6; }
            As[kk][m] = A[(ll)(rowA + m) * saM + (ll)(k0 + kk) * saK];
        }
        #pragma unroll
        for (int r = 0; r < 4; r++) {
            int idx = tid + r * 256;
            int n, kk;
            if (flags & F_BK) { kk = idx & 15; n = idx >> 4; }
            else              { n = idx & 63;  kk = idx >> 6; }
            Bs[kk][n] = B[(ll)(k0 + kk) * sbK + (ll)(colB + n) * sbN];
        }
        __syncthreads();

        #pragma unroll
        for (int kk = 0; kk < BK; kk++) {
            float4 a4 = *(const float4*)&As[kk][ty * 4];
            float4 b4 = *(const float4*)&Bs[kk][tx * 4];
            float av[4] = {a4.x, a4.y, a4.z, a4.w};
            float bv[4] = {b4.x, b4.y, b4.z, b4.w};
            #pragma unroll
            for (int i = 0; i < 4; i++)
                #pragma unroll
                for (int j = 0; j < 4; j++)
                    acc[i][j] += av[i] * bv[j];
        }
        __syncthreads();
    }

    #pragma unroll
    for (int i = 0; i < 4; i++) {
        ll m = rowA + ty * 4 + i;
        #pragma unroll
        for (int j = 0; j < 4; j++) {
            ll n = colB + tx * 4 + j;
            C[m * scM + n * scN] = alpha * acc[i][j];
        }
    }
}

// ---------------- causal softmax (also zeroes s > t) ----------------
__global__ void __launch_bounds__(256)
softmax_causal_k(float* __restrict__ S)
{
    const int t = blockIdx.x;
    const ll z = blockIdx.y;
    float* row = S + (z * T_LEN + t) * (ll)T_LEN;
    const int len = t + 1;
    const int tid = threadIdx.x;

    __shared__ float red[8];

    float m = -1e30f;
    for (int i = tid; i < len; i += 256) m = fmaxf(m, row[i]);
    #pragma unroll
    for (int o = 16; o; o >>= 1) m = fmaxf(m, __shfl_xor_sync(0xffffffffu, m, o));
    if ((tid & 31) == 0) red[tid >> 5] = m;
    __syncthreads();
    float mx = red[0];
    #pragma unroll
    for (int i = 1; i < 8; i++) mx = fmaxf(mx, red[i]);
    __syncthreads();

    float s = 0.f;
    for (int i = tid; i < len; i += 256) {
        float e = __expf(row[i] - mx);
        row[i] = e;
        s += e;
    }
    #pragma unroll
    for (int o = 16; o; o >>= 1) s += __shfl_xor_sync(0xffffffffu, s, o);
    if ((tid & 31) == 0) red[tid >> 5] = s;
    __syncthreads();
    float sum = 0.f;
    #pragma unroll
    for (int i = 0; i < 8; i++) sum += red[i];
    const float inv = 1.f / sum;

    for (int i = tid; i < len; i += 256) row[i] *= inv;
    for (int i = len + tid; i < T_LEN; i += 256) row[i] = 0.f;
}

// ---------------- RoPE kernels ----------------
__global__ void rope_k_kernel(const float* __restrict__ ckr,
                              const float* __restrict__ cosp,
                              const float* __restrict__ sinp,
                              float* __restrict__ Kbig)
{
    int bt = blockIdx.x;
    int i = threadIdx.x;
    int t = bt & (T_LEN - 1);
    float re = ckr[bt * 64 + 2 * i];
    float im = ckr[bt * 64 + 2 * i + 1];
    float c = cosp[t * 32 + i];
    float s = sinp[t * 32 + i];
    float* o = Kbig + (ll)bt * DQK + 512;
    o[2 * i]     = re * c - im * s;
    o[2 * i + 1] = re * s + im * c;
}

__global__ void rope_q_kernel(const float* __restrict__ cqr,
                              const float* __restrict__ cosp,
                              const float* __restrict__ sinp,
                              float* __restrict__ Qbig, float scale)
{
    int bt = blockIdx.x;
    int b = bt >> 11, t = bt & (T_LEN - 1);
    int h = threadIdx.x >> 5, i = threadIdx.x & 31;
    ll base = (ll)bt * 1024 + h * 64;
    float re = cqr[base + 2 * i];
    float im = cqr[base + 2 * i + 1];
    float c = cosp[t * 32 + i];
    float s = sinp[t * 32 + i];
    ll zz = (ll)(b * 16 + h);
    float* o = Qbig + zz * (T_LEN * (ll)DQK) + (ll)t * DQK + 512;
    o[2 * i]     = scale * (re * c - im * s);
    o[2 * i + 1] = scale * (re * s + im * c);
}

// ---------------- host-side launchers ----------------
static void gemm128(int M, int N, int K,
                    const float* A, int saM, int saK, ll saZ1, ll saZ2,
                    const float* B, int sbK, int sbN, ll sbZ1, ll sbZ2,
                    float* C, int scM, int scN, ll scZ1, ll scZ2,
                    int batch, int zdiv, float alpha, int flags)
{
    dim3 grid(N / GBN, M / GBM, batch);
    gemm128_k<<<grid, 256>>>(M, N, K,
                             A, saM, saK, saZ1, saZ2,
                             B, sbK, sbN, sbZ1, sbZ2,
                             C, scM, scN, scZ1, scZ2,
                             zdiv, alpha, flags);
}

static void gemm64(int M, int N, int K,
                   const float* A, int saM, int saK, ll saZ1, ll saZ2,
                   const float* B, int sbK, int sbN, ll sbZ1, ll sbZ2,
                   float* C, int scM, int scN, ll scZ1, ll scZ2,
                   int batch, int zdiv, float alpha, int flags)
{
    dim3 grid(N / BN, M / BM, batch);
    gemm_k<<<grid, 256>>>(M, N, K,
                          A, saM, saK, saZ1, saZ2,
                          B, sbK, sbN, sbZ1, sbZ2,
                          C, scM, scN, scZ1, scZ2,
                          zdiv, alpha, flags);
}

extern "C" void kernel_launch(void* const* d_in, const int* in_sizes, int n_in,
                              void* d_out, int out_size)
{
    const float* x    = (const float*)d_in[0];
    const float* cosp = (const float*)d_in[1];
    const float* sinp = (const float*)d_in[2];
    const float* W_dq = (const float*)d_in[3];
    const float* W_uq = (const float*)d_in[4];
    const float* W_dkv= (const float*)d_in[5];
    const float* W_uk = (const float*)d_in[6];
    const float* W_uv = (const float*)d_in[7];
    const float* W_qr = (const float*)d_in[8];
    const float* W_kr = (const float*)d_in[9];
    const float* W_o  = (const float*)d_in[10];
    float* y = (float*)d_out;

    float *cq, *ckr, *cqr, *Kbig, *Qbig, *keff, *veff, *scores, *ctx;
    cudaGetSymbolAddress((void**)&cq,    g_cq);
    cudaGetSymbolAddress((void**)&ckr,   g_ckr);
    cudaGetSymbolAddress((void**)&cqr,   g_cqr);
    cudaGetSymbolAddress((void**)&Kbig,  g_Kbig);
    cudaGetSymbolAddress((void**)&Qbig,  g_Qbig);
    cudaGetSymbolAddress((void**)&keff,  g_keff);
    cudaGetSymbolAddress((void**)&veff,  g_veff);
    cudaGetSymbolAddress((void**)&scores,g_scores);
    cudaGetSymbolAddress((void**)&ctx,   g_ctx);

    const float scale = 1.0f / sqrtf(192.0f);   // 1/sqrt(HS + DHR)

    // 1) c_q = x @ W_dq^T      (4096 x 512, K=2048)
    gemm128(4096, 512, 2048,
            x,    2048, 1, 0, 0,
            W_dq, 1, 2048, 0, 0,
            cq,   512, 1, 0, 0,
            1, 1, 1.0f, F_AK | F_BK);

    // 2) c_kv = x @ W_dkv^T -> Kbig[:, 0:512]
    gemm128(4096, 512, 2048,
            x,     2048, 1, 0, 0,
            W_dkv, 1, 2048, 0, 0,
            Kbig,  DQK, 1, 0, 0,
            1, 1, 1.0f, F_AK | F_BK);

    // 3) c_kr = x @ W_kr^T     (4096 x 64) — tiny, legacy kernel
    gemm64(4096, 64, 2048,
           x,    2048, 1, 0, 0,
           W_kr, 1, 2048, 0, 0,
           ckr,  64, 1, 0, 0,
           1, 1, 1.0f, F_AK | F_BK);

    // 4) k_eff[h] = W_uq_slice(512x128) @ W_uk_slice(128x512)
    gemm128(512, 512, 128,
            W_uq, 2048, 1, 0, 128,
            W_uk, 512, 1, 0, 65536,
            keff, 512, 1, 0, 262144,
            16, 16, 1.0f, F_AK);

    // 5) v_eff[h] : (512 x 128) = W_uv^T @ W_o_slice^T
    gemm128(512, 128, 2048,
            W_uv, 1, 512, 0, 0,
            W_o,  1, 2048, 0, (ll)128 * 2048,
            veff, 128, 1, 0, 65536,
            16, 16, 1.0f, F_BK);

    // 6) Qbig latent: scale * c_q[b] @ k_eff[h]  -> Qbig[z, t, 0:512]
    gemm128(2048, 512, 512,
            cq,   512, 1, (ll)2048 * 512, 0,
            keff, 512, 1, 0, 262144,
            Qbig, DQK, 1, (ll)16 * 2048 * DQK, (ll)2048 * DQK,
            32, 16, scale, F_AK);

    // 7) c_qr = c_q @ W_qr^T   (4096 x 1024, K=512)
    gemm128(4096, 1024, 512,
            cq,   512, 1, 0, 0,
            W_qr, 1, 512, 0, 0,
            cqr,  1024, 1, 0, 0,
            1, 1, 1.0f, F_AK | F_BK);

    // 8) RoPE
    rope_k_kernel<<<BT, 32>>>(ckr, cosp, sinp, Kbig);
    rope_q_kernel<<<BT, 512>>>(cqr, cosp, sinp, Qbig, scale);

    // 9) scores = Qbig @ Kbig^T  (2048x2048, K=576, batch 32, causal)
    gemm128(2048, 2048, DQK,
            Qbig, DQK, 1, (ll)16 * 2048 * DQK, (ll)2048 * DQK,
            Kbig, 1, DQK, (ll)2048 * DQK, 0,
            scores, 2048, 1, (ll)16 * 2048 * 2048, (ll)2048 * 2048,
            32, 16, 1.0f, F_CAUSAL | F_AK | F_BK);

    // 10) causal softmax (writes zeros for s > t)
    softmax_causal_k<<<dim3(T_LEN, 32), 256>>>(scores);

    // 11) ctx = P @ c_kv   (2048 x 512, K truncated per row tile)
    gemm128(2048, 512, 2048,
            scores, 2048, 1, (ll)16 * 2048 * 2048, (ll)2048 * 2048,
            Kbig, DQK, 1, (ll)2048 * DQK, 0,
            ctx,  512, 1, (ll)16 * 2048 * 512, (ll)2048 * 512,
            32, 16, 1.0f, F_KTRUNC | F_AK);

    // 12) y[b, t, h*128 : h*128+128] = ctx[z] @ v_eff[h]
    gemm128(2048, 128, 512,
            ctx,  512, 1, (ll)16 * 2048 * 512, (ll)2048 * 512,
            veff, 128, 1, 0, 65536,
            y,    2048, 1, (ll)2048 * 2048, 128,
            32, 16, 1.0f, F_AK);
}

// round 10
// speedup vs baseline: 1.6454x; 1.6454x over previous
#include <cuda_runtime.h>
#include <math.h>

// ---------------- problem constants ----------------
// B=2, T=2048, C=2048, NH=16, HS=128, NLQ=512, NLKV=512, DHR=64
#define T_LEN 2048
#define BT    4096          // B*T
#define DQK   576           // 512 latent + 64 rope

typedef long long ll;

// ---------------- scratch (device globals; no allocs allowed) ----------------
__device__ float g_cq   [4096 * 512];          // c_q              (B*T, 512)
__device__ float g_ckr  [4096 * 64];           // c_kr             (B*T, 64)
__device__ float g_cqr  [4096 * 1024];         // c_qr             (B*T, 1024)
__device__ float g_Kbig [2 * 2048 * 576];      // [c_kv | rope(kr)] per (b,s)
__device__ float g_Qbig [32 * 2048 * 576];     // per (b,h,t): [scale*qk | scale*rope(qr)]
__device__ float g_keff [16 * 512 * 512];      // k_eff[h,q,k]
__device__ float g_veff [16 * 512 * 128];      // v_eff[h,k,d]
__device__ float g_scores[32 * 2048 * 2048];   // attention probs (512 MB)
__device__ float g_ctx  [32 * 2048 * 512];     // ctx[b,h,t,k]

#define F_CAUSAL 1   // skip tiles strictly above diagonal
#define F_KTRUNC 2   // limit K loop to (bm+1)*tile  (P@V: P zero beyond s=t)
#define F_AK     4   // A: k contiguous (saK==1)   else m contiguous (saM==1)
#define F_BK     8   // B: k contiguous (sbK==1)   else n contiguous (sbN==1)

// =====================================================================
// 128x128x8 double-buffered fp32 GEMM, 256 threads, 8x8 per thread
// (as 2x2 quads of 4x4 for conflict-free LDS.128). Requires:
//   M % 128 == 0, N % 128 == 0, K % 8 == 0
//   float4-alignment of all operand rows (all strides multiples of 4)
// =====================================================================
#define GBM 128
#define GBN 128
#define GBK 8

__global__ void __launch_bounds__(256)
gemm128_k(int M, int N, int K,
          const float* __restrict__ A, int saM, int saK, ll saZ1, ll saZ2,
          const float* __restrict__ B, int sbK, int sbN, ll sbZ1, ll sbZ2,
          float* __restrict__ C, int scM, int scN, ll scZ1, ll scZ2,
          int zdiv, float alpha, int flags)
{
    const int bn = blockIdx.x, bm = blockIdx.y, z = blockIdx.z;
    if ((flags & F_CAUSAL) && bn > bm) return;

    const int z1 = z / zdiv, z2 = z % zdiv;
    A += z1 * saZ1 + z2 * saZ2;
    B += z1 * sbZ1 + z2 * sbZ2;
    C += z1 * scZ1 + z2 * scZ2;

    const int Kuse = (flags & F_KTRUNC) ? min(K, (bm + 1) * GBM) : K;

    __shared__ float As[2][GBK][GBM];
    __shared__ float Bs[2][GBK][GBN];

    const int tid = threadIdx.x;
    const int tx = tid & 15, ty = tid >> 4;
    const int rowA = bm * GBM;
    const int colB = bn * GBN;

    // global-load index precompute
    const int aM  = tid >> 1;            // F_AK path: row
    const int aK4 = (tid & 1) * 4;       // F_AK path: k quad
    const int aM4 = (tid & 31) * 4;      // m-contig path
    const int aKK = tid >> 5;
    const int bN  = tid >> 1;
    const int bK4 = (tid & 1) * 4;
    const int bN4 = (tid & 31) * 4;
    const int bKK = tid >> 5;

    float acc[2][2][4][4] = {};

    float4 pa, pb;
    // prologue load (k0 = 0)
    if (flags & F_AK) pa = *(const float4*)&A[(ll)(rowA + aM) * saM + aK4];
    else              pa = *(const float4*)&A[(ll)aKK * saK + (rowA + aM4)];
    if (flags & F_BK) pb = *(const float4*)&B[(ll)(colB + bN) * sbN + bK4];
    else              pb = *(const float4*)&B[(ll)bKK * sbK + (colB + bN4)];

    if (flags & F_AK) {
        As[0][aK4 + 0][aM] = pa.x; As[0][aK4 + 1][aM] = pa.y;
        As[0][aK4 + 2][aM] = pa.z; As[0][aK4 + 3][aM] = pa.w;
    } else {
        *(float4*)&As[0][aKK][aM4] = pa;
    }
    if (flags & F_BK) {
        Bs[0][bK4 + 0][bN] = pb.x; Bs[0][bK4 + 1][bN] = pb.y;
        Bs[0][bK4 + 2][bN] = pb.z; Bs[0][bK4 + 3][bN] = pb.w;
    } else {
        *(float4*)&Bs[0][bKK][bN4] = pb;
    }
    __syncthreads();

    int buf = 0;
    for (int k0 = 0; k0 < Kuse; k0 += GBK) {
        const bool nxt = (k0 + GBK) < Kuse;
        if (nxt) {
            const int kn = k0 + GBK;
            if (flags & F_AK) pa = *(const float4*)&A[(ll)(rowA + aM) * saM + (kn + aK4)];
            else              pa = *(const float4*)&A[(ll)(kn + aKK) * saK + (rowA + aM4)];
            if (flags & F_BK) pb = *(const float4*)&B[(ll)(colB + bN) * sbN + (kn + bK4)];
            else              pb = *(const float4*)&B[(ll)(kn + bKK) * sbK + (colB + bN4)];
        }

        #pragma unroll
        for (int kk = 0; kk < GBK; kk++) {
            float4 a0 = *(const float4*)&As[buf][kk][ty * 4];
            float4 a1 = *(const float4*)&As[buf][kk][64 + ty * 4];
            float4 b0 = *(const float4*)&Bs[buf][kk][tx * 4];
            float4 b1 = *(const float4*)&Bs[buf][kk][64 + tx * 4];
            float av[2][4] = {{a0.x, a0.y, a0.z, a0.w}, {a1.x, a1.y, a1.z, a1.w}};
            float bv[2][4] = {{b0.x, b0.y, b0.z, b0.w}, {b1.x, b1.y, b1.z, b1.w}};
            #pragma unroll
            for (int ih = 0; ih < 2; ih++)
                #pragma unroll
                for (int i = 0; i < 4; i++)
                    #pragma unroll
                    for (int jh = 0; jh < 2; jh++)
                        #pragma unroll
                        for (int j = 0; j < 4; j++)
                            acc[ih][jh][i][j] += av[ih][i] * bv[jh][j];
        }

        if (nxt) {
            const int nb = buf ^ 1;
            if (flags & F_AK) {
                As[nb][aK4 + 0][aM] = pa.x; As[nb][aK4 + 1][aM] = pa.y;
                As[nb][aK4 + 2][aM] = pa.z; As[nb][aK4 + 3][aM] = pa.w;
            } else {
                *(float4*)&As[nb][aKK][aM4] = pa;
            }
            if (flags & F_BK) {
                Bs[nb][bK4 + 0][bN] = pb.x; Bs[nb][bK4 + 1][bN] = pb.y;
                Bs[nb][bK4 + 2][bN] = pb.z; Bs[nb][bK4 + 3][bN] = pb.w;
            } else {
                *(float4*)&Bs[nb][bKK][bN4] = pb;
            }
        }
        __syncthreads();
        buf ^= 1;
    }

    // ---- epilogue ----
    if (scN == 1) {
        #pragma unroll
        for (int ih = 0; ih < 2; ih++)
            #pragma unroll
            for (int i = 0; i < 4; i++) {
                ll row = rowA + ih * 64 + ty * 4 + i;
                #pragma unroll
                for (int jh = 0; jh < 2; jh++) {
                    ll col = colB + jh * 64 + tx * 4;
                    float4 v = make_float4(alpha * acc[ih][jh][i][0],
                                           alpha * acc[ih][jh][i][1],
                                           alpha * acc[ih][jh][i][2],
                                           alpha * acc[ih][jh][i][3]);
                    *(float4*)&C[row * scM + col] = v;
                }
            }
    } else {
        #pragma unroll
        for (int ih = 0; ih < 2; ih++)
            #pragma unroll
            for (int i = 0; i < 4; i++) {
                ll row = rowA + ih * 64 + ty * 4 + i;
                #pragma unroll
                for (int jh = 0; jh < 2; jh++)
                    #pragma unroll
                    for (int j = 0; j < 4; j++) {
                        ll col = colB + jh * 64 + tx * 4 + j;
                        C[row * scM + col * scN] = alpha * acc[ih][jh][i][j];
                    }
            }
    }
}

// =====================================================================
// legacy 64x64x16 kernel — kept for the one N=64 GEMM (c_kr)
// =====================================================================
#define BM 64
#define BN 64
#define BK 16

__global__ void __launch_bounds__(256)
gemm_k(int M, int N, int K,
       const float* __restrict__ A, int saM, int saK, ll saZ1, ll saZ2,
       const float* __restrict__ B, int sbK, int sbN, ll sbZ1, ll sbZ2,
       float* __restrict__ C, int scM, int scN, ll scZ1, ll scZ2,
       int zdiv, float alpha, int flags)
{
    const int bn = blockIdx.x, bm = blockIdx.y, z = blockIdx.z;
    if ((flags & F_CAUSAL) && bn > bm) return;

    const int z1 = z / zdiv, z2 = z % zdiv;
    A += z1 * saZ1 + z2 * saZ2;
    B += z1 * sbZ1 + z2 * sbZ2;
    C += z1 * scZ1 + z2 * scZ2;

    const int Kuse = (flags & F_KTRUNC) ? min(K, (bm + 1) * BM) : K;

    __shared__ float As[BK][BM + 4];
    __shared__ float Bs[BK][BN + 4];

    const int tid = threadIdx.x;
    const int tx = tid & 15, ty = tid >> 4;
    const int rowA = bm * BM;
    const int colB = bn * BN;

    float acc[4][4] = {};

    for (int k0 = 0; k0 < Kuse; k0 += BK) {
        #pragma unroll
        for (int r = 0; r < 4; r++) {
            int idx = tid + r * 256;
            int m, kk;
            if (flags & F_AK) { kk = idx & 15; m = idx >> 4; }
            else              { m = idx & 63;  kk = idx >> 6; }
            As[kk][m] = A[(ll)(rowA + m) * saM + (ll)(k0 + kk) * saK];
        }
        #pragma unroll
        for (int r = 0; r < 4; r++) {
            int idx = tid + r * 256;
            int n, kk;
            if (flags & F_BK) { kk = idx & 15; n = idx >> 4; }
            else              { n = idx & 63;  kk = idx >> 6; }
            Bs[kk][n] = B[(ll)(k0 + kk) * sbK + (ll)(colB + n) * sbN];
        }
        __syncthreads();

        #pragma unroll
        for (int kk = 0; kk < BK; kk++) {
            float4 a4 = *(const float4*)&As[kk][ty * 4];
            float4 b4 = *(const float4*)&Bs[kk][tx * 4];
            float av[4] = {a4.x, a4.y, a4.z, a4.w};
            float bv[4] = {b4.x, b4.y, b4.z, b4.w};
            #pragma unroll
            for (int i = 0; i < 4; i++)
                #pragma unroll
                for (int j = 0; j < 4; j++)
                    acc[i][j] += av[i] * bv[j];
        }
        __syncthreads();
    }

    #pragma unroll
    for (int i = 0; i < 4; i++) {
        ll m = rowA + ty * 4 + i;
        #pragma unroll
        for (int j = 0; j < 4; j++) {
            ll n = colB + tx * 4 + j;
            C[m * scM + n * scN] = alpha * acc[i][j];
        }
    }
}

// ---------------- causal softmax (also zeroes s > t) ----------------
__global__ void __launch_bounds__(256)
softmax_causal_k(float* __restrict__ S)
{
    const int t = blockIdx.x;
    const ll z = blockIdx.y;
    float* row = S + (z * T_LEN + t) * (ll)T_LEN;
    const int len = t + 1;
    const int tid = threadIdx.x;

    __shared__ float red[8];

    float m = -1e30f;
    for (int i = tid; i < len; i += 256) m = fmaxf(m, row[i]);
    #pragma unroll
    for (int o = 16; o; o >>= 1) m = fmaxf(m, __shfl_xor_sync(0xffffffffu, m, o));
    if ((tid & 31) == 0) red[tid >> 5] = m;
    __syncthreads();
    float mx = red[0];
    #pragma unroll
    for (int i = 1; i < 8; i++) mx = fmaxf(mx, red[i]);
    __syncthreads();

    float s = 0.f;
    for (int i = tid; i < len; i += 256) {
        float e = __expf(row[i] - mx);
        row[i] = e;
        s += e;
    }
    #pragma unroll
    for (int o = 16; o; o >>= 1) s += __shfl_xor_sync(0xffffffffu, s, o);
    if ((tid & 31) == 0) red[tid >> 5] = s;
    __syncthreads();
    float sum = 0.f;
    #pragma unroll
    for (int i = 0; i < 8; i++) sum += red[i];
    const float inv = 1.f / sum;

    for (int i = tid; i < len; i += 256) row[i] *= inv;
    for (int i = len + tid; i < T_LEN; i += 256) row[i] = 0.f;
}

// ---------------- RoPE kernels ----------------
__global__ void rope_k_kernel(const float* __restrict__ ckr,
                              const float* __restrict__ cosp,
                              const float* __restrict__ sinp,
                              float* __restrict__ Kbig)
{
    int bt = blockIdx.x;
    int i = threadIdx.x;
    int t = bt & (T_LEN - 1);
    float re = ckr[bt * 64 + 2 * i];
    float im = ckr[bt * 64 + 2 * i + 1];
    float c = cosp[t * 32 + i];
    float s = sinp[t * 32 + i];
    float* o = Kbig + (ll)bt * DQK + 512;
    o[2 * i]     = re * c - im * s;
    o[2 * i + 1] = re * s + im * c;
}

__global__ void rope_q_kernel(const float* __restrict__ cqr,
                              const float* __restrict__ cosp,
                              const float* __restrict__ sinp,
                              float* __restrict__ Qbig, float scale)
{
    int bt = blockIdx.x;
    int b = bt >> 11, t = bt & (T_LEN - 1);
    int h = threadIdx.x >> 5, i = threadIdx.x & 31;
    ll base = (ll)bt * 1024 + h * 64;
    float re = cqr[base + 2 * i];
    float im = cqr[base + 2 * i + 1];
    float c = cosp[t * 32 + i];
    float s = sinp[t * 32 + i];
    ll zz = (ll)(b * 16 + h);
    float* o = Qbig + zz * (T_LEN * (ll)DQK) + (ll)t * DQK + 512;
    o[2 * i]     = scale * (re * c - im * s);
    o[2 * i + 1] = scale * (re * s + im * c);
}

// ---------------- host-side launchers ----------------
static void gemm128(int M, int N, int K,
                    const float* A, int saM, int saK, ll saZ1, ll saZ2,
                    const float* B, int sbK, int sbN, ll sbZ1, ll sbZ2,
                    float* C, int scM, int scN, ll scZ1, ll scZ2,
                    int batch, int zdiv, float alpha, int flags)
{
    dim3 grid(N / GBN, M / GBM, batch);
    gemm128_k<<<grid, 256>>>(M, N, K,
                             A, saM, saK, saZ1, saZ2,
                             B, sbK, sbN, sbZ1, sbZ2,
                             C, scM, scN, scZ1, scZ2,
                             zdiv, alpha, flags);
}

static void gemm64(int M, int N, int K,
                   const float* A, int saM, int saK, ll saZ1, ll saZ2,
                   const float* B, int sbK, int sbN, ll sbZ1, ll sbZ2,
                   float* C, int scM, int scN, ll scZ1, ll scZ2,
                   int batch, int zdiv, float alpha, int flags)
{
    dim3 grid(N / BN, M / BM, batch);
    gemm_k<<<grid, 256>>>(M, N, K,
                          A, saM, saK, saZ1, saZ2,
                          B, sbK, sbN, sbZ1, sbZ2,
                          C, scM, scN, scZ1, scZ2,
                          zdiv, alpha, flags);
}

extern "C" void kernel_launch(void* const* d_in, const int* in_sizes, int n_in,
                              void* d_out, int out_size)
{
    const float* x    = (const float*)d_in[0];
    const float* cosp = (const float*)d_in[1];
    const float* sinp = (const float*)d_in[2];
    const float* W_dq = (const float*)d_in[3];
    const float* W_uq = (const float*)d_in[4];
    const float* W_dkv= (const float*)d_in[5];
    const float* W_uk = (const float*)d_in[6];
    const float* W_uv = (const float*)d_in[7];
    const float* W_qr = (const float*)d_in[8];
    const float* W_kr = (const float*)d_in[9];
    const float* W_o  = (const float*)d_in[10];
    float* y = (float*)d_out;

    float *cq, *ckr, *cqr, *Kbig, *Qbig, *keff, *veff, *scores, *ctx;
    cudaGetSymbolAddress((void**)&cq,    g_cq);
    cudaGetSymbolAddress((void**)&ckr,   g_ckr);
    cudaGetSymbolAddress((void**)&cqr,   g_cqr);
    cudaGetSymbolAddress((void**)&Kbig,  g_Kbig);
    cudaGetSymbolAddress((void**)&Qbig,  g_Qbig);
    cudaGetSymbolAddress((void**)&keff,  g_keff);
    cudaGetSymbolAddress((void**)&veff,  g_veff);
    cudaGetSymbolAddress((void**)&scores,g_scores);
    cudaGetSymbolAddress((void**)&ctx,   g_ctx);

    const float scale = 1.0f / sqrtf(192.0f);   // 1/sqrt(HS + DHR)

    // 1) c_q = x @ W_dq^T      (4096 x 512, K=2048)
    gemm128(4096, 512, 2048,
            x,    2048, 1, 0, 0,
            W_dq, 1, 2048, 0, 0,
            cq,   512, 1, 0, 0,
            1, 1, 1.0f, F_AK | F_BK);

    // 2) c_kv = x @ W_dkv^T -> Kbig[:, 0:512]
    gemm128(4096, 512, 2048,
            x,     2048, 1, 0, 0,
            W_dkv, 1, 2048, 0, 0,
            Kbig,  DQK, 1, 0, 0,
            1, 1, 1.0f, F_AK | F_BK);

    // 3) c_kr = x @ W_kr^T     (4096 x 64) — tiny, legacy kernel
    gemm64(4096, 64, 2048,
           x,    2048, 1, 0, 0,
           W_kr, 1, 2048, 0, 0,
           ckr,  64, 1, 0, 0,
           1, 1, 1.0f, F_AK | F_BK);

    // 4) k_eff[h] = W_uq_slice(512x128) @ W_uk_slice(128x512)
    gemm128(512, 512, 128,
            W_uq, 2048, 1, 0, 128,
            W_uk, 512, 1, 0, 65536,
            keff, 512, 1, 0, 262144,
            16, 16, 1.0f, F_AK);

    // 5) v_eff[h] : (512 x 128) = W_uv^T @ W_o_slice^T
    gemm128(512, 128, 2048,
            W_uv, 1, 512, 0, 0,
            W_o,  1, 2048, 0, (ll)128 * 2048,
            veff, 128, 1, 0, 65536,
            16, 16, 1.0f, F_BK);

    // 6) Qbig latent: scale * c_q[b] @ k_eff[h]  -> Qbig[z, t, 0:512]
    gemm128(2048, 512, 512,
            cq,   512, 1, (ll)2048 * 512, 0,
            keff, 512, 1, 0, 262144,
            Qbig, DQK, 1, (ll)16 * 2048 * DQK, (ll)2048 * DQK,
            32, 16, scale, F_AK);

    // 7) c_qr = c_q @ W_qr^T   (4096 x 1024, K=512)
    gemm128(4096, 1024, 512,
            cq,   512, 1, 0, 0,
            W_qr, 1, 512, 0, 0,
            cqr,  1024, 1, 0, 0,
            1, 1, 1.0f, F_AK | F_BK);

    // 8) RoPE
    rope_k_kernel<<<BT, 32>>>(ckr, cosp, sinp, Kbig);
    rope_q_kernel<<<BT, 512>>>(cqr, cosp, sinp, Qbig, scale);

    // 9) scores = Qbig @ Kbig^T  (2048x2048, K=576, batch 32, causal)
    gemm128(2048, 2048, DQK,
            Qbig, DQK, 1, (ll)16 * 2048 * DQK, (ll)2048 * DQK,
            Kbig, 1, DQK, (ll)2048 * DQK, 0,
            scores, 2048, 1, (ll)16 * 2048 * 2048, (ll)2048 * 2048,
            32, 16, 1.0f, F_CAUSAL | F_AK | F_BK);

    // 10) causal softmax (writes zeros for s > t)
    softmax_causal_k<<<dim3(T_LEN, 32), 256>>>(scores);

    // 11) ctx = P @ c_kv   (2048 x 512, K truncated per row tile)
    gemm128(2048, 512, 2048,
            scores, 2048, 1, (ll)16 * 2048 * 2048, (ll)2048 * 2048,
            Kbig, DQK, 1, (ll)2048 * DQK, 0,
            ctx,  512, 1, (ll)16 * 2048 * 512, (ll)2048 * 512,
            32, 16, 1.0f, F_KTRUNC | F_AK);

    // 12) y[b, t, h*128 : h*128+128] = ctx[z] @ v_eff[h]
    gemm128(2048, 128, 512,
            ctx,  512, 1, (ll)16 * 2048 * 512, (ll)2048 * 512,
            veff, 128, 1, 0, 65536,
            y,    2048, 1, (ll)2048 * 2048, 128,
            32, 16, 1.0f, F_AK);
}